// round 2
// baseline (speedup 1.0000x reference)
#include <cuda_runtime.h>
#include <stdint.h>
#include <math.h>

#define BATCH   256
#define NQ      1000
#define NC      81
#define NELEM   (NQ*NC)     /* 81000 */
#define NV4     (NELEM/4)   /* 20250 */
#define KTOP    100
#define NT      1024
#define CANDBUF 1024

__device__ __forceinline__ float sigm(float x) { return 1.0f / (1.0f + expf(-x)); }

__global__ void __launch_bounds__(NT)
postproc_kernel(const float* __restrict__ logits,   // [B,Q,C]
                const float* __restrict__ obj,      // [B,Q]
                const float* __restrict__ boxesIn,  // [B,Q,4]
                const float* __restrict__ unk,      // [B,Q]
                const float* __restrict__ tsz,      // [B,2]
                float* __restrict__ out)
{
    const int b   = blockIdx.x;
    const int tid = threadIdx.x;

    __shared__ float    fac[NQ];     // exp(-obj)*(1-sig(unk))
    __shared__ float    lastv[NQ];   // exp(-obj)*sig(unk)
    __shared__ unsigned warpcnt[32];
    __shared__ unsigned s_bcast;
    __shared__ unsigned s_cnt;
    __shared__ unsigned cbits[CANDBUF];
    __shared__ unsigned cidx[CANDBUF];

    // ---- per-query factors ----
    for (int q = tid; q < NQ; q += NT) {
        float o  = obj[b * NQ + q];
        float uu = unk[b * NQ + q];
        float op = expf(-o);
        float su = sigm(uu);
        fac[q]   = op * (1.0f - su);
        lastv[q] = op * su;
    }
    if (tid == 0) s_cnt = 0;
    __syncthreads();

    // ---- single pass over logits: per-thread top-4 (bits, idx) ----
    unsigned b0 = 0, b1 = 0, b2 = 0, b3 = 0;            // prob float bits (>=0 so uint order == float order)
    unsigned i0 = 0xFFFFFFFFu, i1 = 0xFFFFFFFFu, i2 = 0xFFFFFFFFu, i3 = 0xFFFFFFFFu;

    const float4* L4 = (const float4*)(logits + (size_t)b * NELEM);

    for (int v = tid; v < NV4; v += NT) {
        float4 x = L4[v];
        unsigned e0 = 4u * (unsigned)v;
        float lv[4] = { x.x, x.y, x.z, x.w };
        #pragma unroll
        for (int k = 0; k < 4; k++) {
            unsigned e = e0 + (unsigned)k;
            unsigned q = e / 81u;
            unsigned c = e - q * 81u;
            float p;
            if (c < 60u)       p = fac[q] * sigm(lv[k]);
            else if (c == 80u) p = lastv[q];
            else               p = 0.0f;
            unsigned pb = __float_as_uint(p);
            if (pb > b3) {                      // strictly greater keeps earlier index on ties
                if (pb > b1) {
                    if (pb > b0) { b3=b2;i3=i2; b2=b1;i2=i1; b1=b0;i1=i0; b0=pb;i0=e; }
                    else         { b3=b2;i3=i2; b2=b1;i2=i1; b1=pb;i1=e; }
                } else {
                    if (pb > b2) { b3=b2;i3=i2; b2=pb;i2=e; }
                    else         { b3=pb;i3=e; }
                }
            }
        }
    }
    __syncthreads();

    // ---- binary search on value bits: T = 100th-largest among the 4096 kept ----
    unsigned lo = 0u, hi = 0x7F800001u;
    const int w = tid >> 5, l = tid & 31;
    while (hi - lo > 1u) {
        unsigned mid = lo + ((hi - lo) >> 1);
        unsigned c = (unsigned)(b0 >= mid) + (unsigned)(b1 >= mid)
                   + (unsigned)(b2 >= mid) + (unsigned)(b3 >= mid);
        #pragma unroll
        for (int o = 16; o > 0; o >>= 1) c += __shfl_down_sync(0xFFFFFFFFu, c, o);
        if (l == 0) warpcnt[w] = c;
        __syncthreads();
        if (w == 0) {
            unsigned s = warpcnt[l];
            #pragma unroll
            for (int o = 16; o > 0; o >>= 1) s += __shfl_down_sync(0xFFFFFFFFu, s, o);
            if (l == 0) s_bcast = s;
        }
        __syncthreads();
        unsigned cnt = s_bcast;
        if (cnt >= KTOP) lo = mid; else hi = mid;
    }
    const unsigned T = lo;    // >=100 elements have bits >= T; T <= global 100th value

    // ---- collect candidates >= T (from registers; flagged threads rescan) ----
    if (b0 >= T) { unsigned p = atomicAdd(&s_cnt, 1u); if (p < CANDBUF) { cbits[p]=b0; cidx[p]=i0; } }
    if (b1 >= T) { unsigned p = atomicAdd(&s_cnt, 1u); if (p < CANDBUF) { cbits[p]=b1; cidx[p]=i1; } }
    if (b2 >= T) { unsigned p = atomicAdd(&s_cnt, 1u); if (p < CANDBUF) { cbits[p]=b2; cidx[p]=i2; } }
    if (b3 >= T) { unsigned p = atomicAdd(&s_cnt, 1u); if (p < CANDBUF) { cbits[p]=b3; cidx[p]=i3; } }

    if (b3 >= T) {
        // this thread may have dropped elements >= T: exact rescan of its strided range
        for (int v = tid; v < NV4; v += NT) {
            float4 x = L4[v];
            unsigned e0 = 4u * (unsigned)v;
            float lv[4] = { x.x, x.y, x.z, x.w };
            #pragma unroll
            for (int k = 0; k < 4; k++) {
                unsigned e = e0 + (unsigned)k;
                unsigned q = e / 81u;
                unsigned c = e - q * 81u;
                float p;
                if (c < 60u)       p = fac[q] * sigm(lv[k]);
                else if (c == 80u) p = lastv[q];
                else               p = 0.0f;
                unsigned pb = __float_as_uint(p);
                if (pb >= T && e != i0 && e != i1 && e != i2 && e != i3) {
                    unsigned pos = atomicAdd(&s_cnt, 1u);
                    if (pos < CANDBUF) { cbits[pos] = pb; cidx[pos] = e; }
                }
            }
        }
    }
    __syncthreads();
    const unsigned nF = (s_cnt < CANDBUF) ? s_cnt : CANDBUF;

    // ---- exact rank ordering (value desc, index asc) and output ----
    const float* Bx = boxesIn + (size_t)b * NQ * 4;
    const float ih = tsz[b * 2 + 0];
    const float iw = tsz[b * 2 + 1];

    for (unsigned i = tid; i < nF; i += NT) {
        unsigned bi = cbits[i], xi = cidx[i];
        unsigned r = 0;
        for (unsigned j = 0; j < nF; j++) {
            unsigned bj = cbits[j], xj = cidx[j];
            r += (bj > bi) || (bj == bi && xj < xi);
        }
        if (r < KTOP) {
            unsigned q = xi / 81u;
            unsigned c = xi - q * 81u;
            out[(size_t)b * KTOP + r]                       = __uint_as_float(bi);
            out[(size_t)BATCH * KTOP + (size_t)b * KTOP + r] = (float)c;
            float cx = Bx[q * 4 + 0], cy = Bx[q * 4 + 1];
            float ww = Bx[q * 4 + 2], hh = Bx[q * 4 + 3];
            float* ob = out + (size_t)2 * BATCH * KTOP + ((size_t)b * KTOP + r) * 4;
            ob[0] = (cx - 0.5f * ww) * iw;
            ob[1] = (cy - 0.5f * hh) * ih;
            ob[2] = (cx + 0.5f * ww) * iw;
            ob[3] = (cy + 0.5f * hh) * ih;
        }
    }
}

extern "C" void kernel_launch(void* const* d_in, const int* in_sizes, int n_in,
                              void* d_out, int out_size)
{
    const float* logits  = (const float*)d_in[0];  // (256,1000,81)
    const float* obj     = (const float*)d_in[1];  // (256,1000)
    const float* boxesIn = (const float*)d_in[2];  // (256,1000,4)
    const float* unk     = (const float*)d_in[3];  // (256,1000)
    const float* tsz     = (const float*)d_in[4];  // (256,2)
    float* out = (float*)d_out;
    (void)in_sizes; (void)n_in; (void)out_size;

    postproc_kernel<<<BATCH, NT>>>(logits, obj, boxesIn, unk, tsz, out);
}

// round 3
// speedup vs baseline: 1.2798x; 1.2798x over previous
#include <cuda_runtime.h>
#include <stdint.h>
#include <math.h>

#define BATCH    256
#define NQ       1000
#define NC       81
#define NELEM    (NQ*NC)     /* 81000 */
#define NV4      (NELEM/4)   /* 20250 */
#define KTOP     100
#define NT       1024
#define CANDBUF  1024
#define NITER_BS 24

__device__ __forceinline__ float sigm_precise(float x) { return 1.0f / (1.0f + expf(-x)); }

__global__ void __launch_bounds__(NT, 2)
postproc_kernel(const float* __restrict__ logits,   // [B,Q,C]
                const float* __restrict__ obj,      // [B,Q]
                const float* __restrict__ boxesIn,  // [B,Q,4]
                const float* __restrict__ unk,      // [B,Q]
                const float* __restrict__ tsz,      // [B,2]
                float* __restrict__ out)
{
    const int b   = blockIdx.x;
    const int tid = threadIdx.x;

    __shared__ float    fac[NQ];     // exp(-obj)*(1-sig(unk))   (PRECISE)
    __shared__ float    lastv[NQ];   // exp(-obj)*sig(unk)       (PRECISE)
    __shared__ unsigned s_sum[NITER_BS];
    __shared__ unsigned s_cnt;
    __shared__ unsigned cbits[CANDBUF];
    __shared__ unsigned cidx[CANDBUF];

    // ---- per-query factors (precise; trivial cost, 1000 queries) ----
    for (int q = tid; q < NQ; q += NT) {
        float o  = obj[b * NQ + q];
        float uu = unk[b * NQ + q];
        float op = expf(-o);
        float su = sigm_precise(uu);
        fac[q]   = op * (1.0f - su);
        lastv[q] = op * su;
    }
    if (tid < NITER_BS) s_sum[tid] = 0;
    if (tid == 0) s_cnt = 0;
    __syncthreads();

    // ---- pass 1: fast-approx scan, per-thread top-4 (bits, idx) ----
    unsigned b0 = 0, b1 = 0, b2 = 0, b3 = 0;
    unsigned i0 = 0xFFFFFFFFu, i1 = 0xFFFFFFFFu, i2 = 0xFFFFFFFFu, i3 = 0xFFFFFFFFu;

    const float4* L4 = (const float4*)(logits + (size_t)b * NELEM);

    {
        unsigned e = 4u * (unsigned)tid;
        unsigned q = e / 81u;            // one real division, then incremental
        unsigned c = e - q * 81u;
        for (int v = tid; v < NV4; v += NT) {
            float4 x = L4[v];
            float lv[4] = { x.x, x.y, x.z, x.w };
            unsigned qq = q, cc = c;
            #pragma unroll
            for (int k = 0; k < 4; k++) {
                float p;
                if (cc < 60u) {
                    float t = __expf(-lv[k]);            // fast
                    p = __fdividef(fac[qq], 1.0f + t);   // fast
                } else if (cc == 80u) {
                    p = lastv[qq];
                } else {
                    p = 0.0f;
                }
                unsigned pb = __float_as_uint(p);
                if (pb > b3) {
                    unsigned ee = 4u * (unsigned)v + (unsigned)k;
                    if (pb > b1) {
                        if (pb > b0) { b3=b2;i3=i2; b2=b1;i2=i1; b1=b0;i1=i0; b0=pb;i0=ee; }
                        else         { b3=b2;i3=i2; b2=b1;i2=i1; b1=pb;i1=ee; }
                    } else {
                        if (pb > b2) { b3=b2;i3=i2; b2=pb;i2=ee; }
                        else         { b3=pb;i3=ee; }
                    }
                }
                ++cc; if (cc == 81u) { cc = 0u; ++qq; }
            }
            c += 46u; q += 50u;               // advance by 4096 elements
            if (c >= 81u) { c -= 81u; ++q; }
        }
    }
    __syncthreads();

    // ---- binary search on approx bits: T with count(approx >= T) >= 100 ----
    unsigned lo = 0u, hi = 0x7F800001u;
    for (int it = 0; it < NITER_BS; ++it) {
        unsigned mid = lo + ((hi - lo) >> 1);
        unsigned cv = (unsigned)(b0 >= mid) + (unsigned)(b1 >= mid)
                    + (unsigned)(b2 >= mid) + (unsigned)(b3 >= mid);
        unsigned cw = __reduce_add_sync(0xFFFFFFFFu, cv);
        if ((tid & 31) == 0) atomicAdd(&s_sum[it], cw);
        __syncthreads();
        unsigned cnt = s_sum[it];
        if (cnt >= KTOP) lo = mid; else hi = mid;
    }
    // margin: kept set provably contains the PRECISE top-100
    unsigned T_keep;
    {
        float tv = __uint_as_float(lo);
        T_keep = __float_as_uint(tv * 0.99998f);   // 2e-5 margin >> 1e-6 approx error
        if (lo == 0u) T_keep = 0u;
    }

    // ---- collect candidate indices (approx >= T_keep) ----
    if (b0 >= T_keep) { unsigned p = atomicAdd(&s_cnt, 1u); if (p < CANDBUF) cidx[p] = i0; }
    if (b1 >= T_keep) { unsigned p = atomicAdd(&s_cnt, 1u); if (p < CANDBUF) cidx[p] = i1; }
    if (b2 >= T_keep) { unsigned p = atomicAdd(&s_cnt, 1u); if (p < CANDBUF) cidx[p] = i2; }
    if (b3 >= T_keep) { unsigned p = atomicAdd(&s_cnt, 1u); if (p < CANDBUF) cidx[p] = i3; }

    if (b3 >= T_keep) {
        // this thread may have dropped qualifying elements: rescan its range (L2-hot)
        unsigned e = 4u * (unsigned)tid;
        unsigned q = e / 81u;
        unsigned c = e - q * 81u;
        for (int v = tid; v < NV4; v += NT) {
            float4 x = L4[v];
            float lv[4] = { x.x, x.y, x.z, x.w };
            unsigned qq = q, cc = c;
            #pragma unroll
            for (int k = 0; k < 4; k++) {
                float p;
                if (cc < 60u) {
                    float t = __expf(-lv[k]);
                    p = __fdividef(fac[qq], 1.0f + t);
                } else if (cc == 80u) {
                    p = lastv[qq];
                } else {
                    p = 0.0f;
                }
                unsigned pb = __float_as_uint(p);
                unsigned ee = 4u * (unsigned)v + (unsigned)k;
                if (pb >= T_keep && ee != i0 && ee != i1 && ee != i2 && ee != i3) {
                    unsigned pos = atomicAdd(&s_cnt, 1u);
                    if (pos < CANDBUF) cidx[pos] = ee;
                }
                ++cc; if (cc == 81u) { cc = 0u; ++qq; }
            }
            c += 46u; q += 50u;
            if (c >= 81u) { c -= 81u; ++q; }
        }
    }
    __syncthreads();
    const unsigned nF = (s_cnt < CANDBUF) ? s_cnt : CANDBUF;

    // ---- recompute candidates PRECISELY (identical formula to verified kernel) ----
    const float* L = logits + (size_t)b * NELEM;
    for (unsigned i = tid; i < nF; i += NT) {
        unsigned e = cidx[i];
        unsigned q = e / 81u;
        unsigned c = e - q * 81u;
        float p;
        if (c < 60u)       p = fac[q] * sigm_precise(L[e]);
        else if (c == 80u) p = lastv[q];
        else               p = 0.0f;
        cbits[i] = __float_as_uint(p);
    }
    __syncthreads();

    // ---- exact rank ordering (precise value desc, index asc) and output ----
    const float* Bx = boxesIn + (size_t)b * NQ * 4;
    const float ih = tsz[b * 2 + 0];
    const float iw = tsz[b * 2 + 1];

    for (unsigned i = tid; i < nF; i += NT) {
        unsigned bi = cbits[i], xi = cidx[i];
        unsigned r = 0;
        for (unsigned j = 0; j < nF; j++) {
            unsigned bj = cbits[j], xj = cidx[j];
            r += (bj > bi) || (bj == bi && xj < xi);
        }
        if (r < KTOP) {
            unsigned q = xi / 81u;
            unsigned c = xi - q * 81u;
            out[(size_t)b * KTOP + r]                        = __uint_as_float(bi);
            out[(size_t)BATCH * KTOP + (size_t)b * KTOP + r] = (float)c;
            float cx = Bx[q * 4 + 0], cy = Bx[q * 4 + 1];
            float ww = Bx[q * 4 + 2], hh = Bx[q * 4 + 3];
            float* ob = out + (size_t)2 * BATCH * KTOP + ((size_t)b * KTOP + r) * 4;
            ob[0] = (cx - 0.5f * ww) * iw;
            ob[1] = (cy - 0.5f * hh) * ih;
            ob[2] = (cx + 0.5f * ww) * iw;
            ob[3] = (cy + 0.5f * hh) * ih;
        }
    }
}

extern "C" void kernel_launch(void* const* d_in, const int* in_sizes, int n_in,
                              void* d_out, int out_size)
{
    const float* logits  = (const float*)d_in[0];  // (256,1000,81)
    const float* obj     = (const float*)d_in[1];  // (256,1000)
    const float* boxesIn = (const float*)d_in[2];  // (256,1000,4)
    const float* unk     = (const float*)d_in[3];  // (256,1000)
    const float* tsz     = (const float*)d_in[4];  // (256,2)
    float* out = (float*)d_out;
    (void)in_sizes; (void)n_in; (void)out_size;

    postproc_kernel<<<BATCH, NT>>>(logits, obj, boxesIn, unk, tsz, out);
}

// round 4
// speedup vs baseline: 1.9362x; 1.5128x over previous
#include <cuda_runtime.h>
#include <stdint.h>
#include <math.h>

#define BATCH    256
#define NQ       1000
#define NC       81
#define NELEM    (NQ*NC)     /* 81000 */
#define NV4      (NELEM/4)   /* 20250 */
#define KTOP     100
#define NT       1024
#define CANDBUF  1024
#define T0_ITERS 16
#define NITER_BS 24

__device__ __forceinline__ float sigm_precise(float x) { return 1.0f / (1.0f + expf(-x)); }

__global__ void __launch_bounds__(NT, 2)
postproc_kernel(const float* __restrict__ logits,   // [B,Q,C]
                const float* __restrict__ obj,      // [B,Q]
                const float* __restrict__ boxesIn,  // [B,Q,4]
                const float* __restrict__ unk,      // [B,Q]
                const float* __restrict__ tsz,      // [B,2]
                float* __restrict__ out)
{
    const int b   = blockIdx.x;
    const int tid = threadIdx.x;

    __shared__ float    fac[NQ + 1];   // exp(-obj)*(1-sig(unk)), PRECISE; fac[NQ]=0 pad
    __shared__ float    lastv[NQ];     // exp(-obj)*sig(unk), PRECISE
    __shared__ unsigned s_sum[T0_ITERS + NITER_BS];
    __shared__ unsigned s_cnt;
    __shared__ unsigned cbits[CANDBUF];
    __shared__ unsigned cidx[CANDBUF];

    // ---- per-query factors (precise) ----
    for (int q = tid; q < NQ; q += NT) {
        float o  = obj[b * NQ + q];
        float uu = unk[b * NQ + q];
        float op = expf(-o);
        float su = sigm_precise(uu);
        fac[q]   = op * (1.0f - su);
        lastv[q] = op * su;
    }
    if (tid < T0_ITERS + NITER_BS) s_sum[tid] = 0;
    if (tid == 0) { s_cnt = 0; fac[NQ] = 0.0f; }
    __syncthreads();

    // ---- T0: 100th-largest lastv (actual achieved values => T0 <= true 100th) ----
    unsigned vL = (tid < NQ) ? __float_as_uint(lastv[tid]) : 0u;
    unsigned lo0 = 0u, hi0 = 0x7F800001u;
    for (int it = 0; it < T0_ITERS; ++it) {
        unsigned mid = lo0 + ((hi0 - lo0) >> 1);
        unsigned cw = __reduce_add_sync(0xFFFFFFFFu, (unsigned)(vL >= mid));
        if ((tid & 31) == 0) atomicAdd(&s_sum[it], cw);
        __syncthreads();
        if (s_sum[it] >= KTOP) lo0 = mid; else hi0 = mid;
    }
    const float T0f = __uint_as_float(lo0);

    // ---- pass 1: group-pruned fast scan, per-thread top-4 (approx bits, idx) ----
    unsigned b0 = 0, b1 = 0, b2 = 0, b3 = 0;
    unsigned i0 = 0xFFFFFFFFu, i1 = 0xFFFFFFFFu, i2 = 0xFFFFFFFFu, i3 = 0xFFFFFFFFu;
    float thrF = T0f;   // skip groups with upper bound < thrF (strict)

    const float4* L4 = (const float4*)(logits + (size_t)b * NELEM);

    {
        unsigned q = (4u * (unsigned)tid) / 81u;
        unsigned c = 4u * (unsigned)tid - q * 81u;
        for (int v = tid; v < NV4; v += NT) {
            float4 x = L4[v];
            unsigned qq = q, cc = c;
            // advance counters for next iteration (stride 4096 elements)
            c += 46u; q += 50u; if (c >= 81u) { c -= 81u; ++q; }

            if (cc >= 60u && cc <= 76u) continue;      // group entirely invalid -> zero

            float f2   = (cc >= 78u) ? fac[qq + 1u] : 0.0f;   // straddles next query?
            float facm = fmaxf(fac[qq], f2);
            float ubL  = (cc >= 77u) ? lastv[qq] : 0.0f;      // group contains c==80?
            if (fmaxf(facm, ubL) < thrF) continue;            // stage 1: sigm<1 bound

            float gmax = fmaxf(fmaxf(x.x, x.y), fmaxf(x.z, x.w));
            float sref = __fdividef(facm, 1.0f + __expf(-gmax)) * 1.0001f;
            if (fmaxf(sref, ubL) < thrF) continue;            // stage 2: refined bound

            // full per-element path (rare)
            float lv[4] = { x.x, x.y, x.z, x.w };
            unsigned q2 = qq, c2 = cc;
            #pragma unroll
            for (int k = 0; k < 4; k++) {
                float p;
                if (c2 < 60u)       p = __fdividef(fac[q2], 1.0f + __expf(-lv[k]));
                else if (c2 == 80u) p = lastv[q2];
                else                p = 0.0f;
                unsigned pb = __float_as_uint(p);
                if (pb > b3) {
                    unsigned ee = 4u * (unsigned)v + (unsigned)k;
                    if (pb > b1) {
                        if (pb > b0) { b3=b2;i3=i2; b2=b1;i2=i1; b1=b0;i1=i0; b0=pb;i0=ee; }
                        else         { b3=b2;i3=i2; b2=b1;i2=i1; b1=pb;i1=ee; }
                    } else {
                        if (pb > b2) { b3=b2;i3=i2; b2=pb;i2=ee; }
                        else         { b3=pb;i3=ee; }
                    }
                    thrF = fmaxf(T0f, __uint_as_float(b3));
                }
                ++c2; if (c2 == 81u) { c2 = 0u; ++q2; }
            }
        }
    }
    __syncthreads();

    // ---- binary search on approx bits: T = 100th-largest among kept values ----
    unsigned lo = 0u, hi = 0x7F800001u;
    for (int it = 0; it < NITER_BS; ++it) {
        unsigned mid = lo + ((hi - lo) >> 1);
        unsigned cv = (unsigned)(b0 >= mid) + (unsigned)(b1 >= mid)
                    + (unsigned)(b2 >= mid) + (unsigned)(b3 >= mid);
        unsigned cw = __reduce_add_sync(0xFFFFFFFFu, cv);
        if ((tid & 31) == 0) atomicAdd(&s_sum[T0_ITERS + it], cw);
        __syncthreads();
        if (s_sum[T0_ITERS + it] >= KTOP) lo = mid; else hi = mid;
    }
    unsigned T_keep;
    {
        float tv = __uint_as_float(lo);
        T_keep = __float_as_uint(tv * 0.99998f);   // 2e-5 margin >> approx error
        if (lo == 0u) T_keep = 0u;
    }

    // ---- collect candidates (approx >= T_keep) ----
    if (b0 >= T_keep) { unsigned p = atomicAdd(&s_cnt, 1u); if (p < CANDBUF) cidx[p] = i0; }
    if (b1 >= T_keep) { unsigned p = atomicAdd(&s_cnt, 1u); if (p < CANDBUF) cidx[p] = i1; }
    if (b2 >= T_keep) { unsigned p = atomicAdd(&s_cnt, 1u); if (p < CANDBUF) cidx[p] = i2; }
    if (b3 >= T_keep) { unsigned p = atomicAdd(&s_cnt, 1u); if (p < CANDBUF) cidx[p] = i3; }

    if (b3 >= T_keep) {
        // thread may have dropped qualifiers: pruned rescan (L2-hot)
        const float thrR = fmaxf(T0f, __uint_as_float(T_keep));
        unsigned q = (4u * (unsigned)tid) / 81u;
        unsigned c = 4u * (unsigned)tid - q * 81u;
        for (int v = tid; v < NV4; v += NT) {
            float4 x = L4[v];
            unsigned qq = q, cc = c;
            c += 46u; q += 50u; if (c >= 81u) { c -= 81u; ++q; }

            if (cc >= 60u && cc <= 76u) continue;
            float f2   = (cc >= 78u) ? fac[qq + 1u] : 0.0f;
            float facm = fmaxf(fac[qq], f2);
            float ubL  = (cc >= 77u) ? lastv[qq] : 0.0f;
            if (fmaxf(facm, ubL) < thrR) continue;
            float gmax = fmaxf(fmaxf(x.x, x.y), fmaxf(x.z, x.w));
            float sref = __fdividef(facm, 1.0f + __expf(-gmax)) * 1.0001f;
            if (fmaxf(sref, ubL) < thrR) continue;

            float lv[4] = { x.x, x.y, x.z, x.w };
            unsigned q2 = qq, c2 = cc;
            #pragma unroll
            for (int k = 0; k < 4; k++) {
                float p;
                if (c2 < 60u)       p = __fdividef(fac[q2], 1.0f + __expf(-lv[k]));
                else if (c2 == 80u) p = lastv[q2];
                else                p = 0.0f;
                unsigned pb = __float_as_uint(p);
                unsigned ee = 4u * (unsigned)v + (unsigned)k;
                if (pb >= T_keep && ee != i0 && ee != i1 && ee != i2 && ee != i3) {
                    unsigned pos = atomicAdd(&s_cnt, 1u);
                    if (pos < CANDBUF) cidx[pos] = ee;
                }
                ++c2; if (c2 == 81u) { c2 = 0u; ++q2; }
            }
        }
    }
    __syncthreads();
    const unsigned nF = (s_cnt < CANDBUF) ? s_cnt : CANDBUF;

    // ---- recompute candidates PRECISELY (bit-identical to verified kernel) ----
    const float* L = logits + (size_t)b * NELEM;
    for (unsigned i = tid; i < nF; i += NT) {
        unsigned e = cidx[i];
        unsigned q = e / 81u;
        unsigned c = e - q * 81u;
        float p;
        if (c < 60u)       p = fac[q] * sigm_precise(L[e]);
        else if (c == 80u) p = lastv[q];
        else               p = 0.0f;
        cbits[i] = __float_as_uint(p);
    }
    __syncthreads();

    // ---- exact rank ordering (precise value desc, index asc) and output ----
    const float* Bx = boxesIn + (size_t)b * NQ * 4;
    const float ih = tsz[b * 2 + 0];
    const float iw = tsz[b * 2 + 1];

    for (unsigned i = tid; i < nF; i += NT) {
        unsigned bi = cbits[i], xi = cidx[i];
        unsigned r = 0;
        for (unsigned j = 0; j < nF; j++) {
            unsigned bj = cbits[j], xj = cidx[j];
            r += (bj > bi) || (bj == bi && xj < xi);
        }
        if (r < KTOP) {
            unsigned q = xi / 81u;
            unsigned c = xi - q * 81u;
            out[(size_t)b * KTOP + r]                        = __uint_as_float(bi);
            out[(size_t)BATCH * KTOP + (size_t)b * KTOP + r] = (float)c;
            float cx = Bx[q * 4 + 0], cy = Bx[q * 4 + 1];
            float ww = Bx[q * 4 + 2], hh = Bx[q * 4 + 3];
            float* ob = out + (size_t)2 * BATCH * KTOP + ((size_t)b * KTOP + r) * 4;
            ob[0] = (cx - 0.5f * ww) * iw;
            ob[1] = (cy - 0.5f * hh) * ih;
            ob[2] = (cx + 0.5f * ww) * iw;
            ob[3] = (cy + 0.5f * hh) * ih;
        }
    }
}

extern "C" void kernel_launch(void* const* d_in, const int* in_sizes, int n_in,
                              void* d_out, int out_size)
{
    const float* logits  = (const float*)d_in[0];  // (256,1000,81)
    const float* obj     = (const float*)d_in[1];  // (256,1000)
    const float* boxesIn = (const float*)d_in[2];  // (256,1000,4)
    const float* unk     = (const float*)d_in[3];  // (256,1000)
    const float* tsz     = (const float*)d_in[4];  // (256,2)
    float* out = (float*)d_out;
    (void)in_sizes; (void)n_in; (void)out_size;

    postproc_kernel<<<BATCH, NT>>>(logits, obj, boxesIn, unk, tsz, out);
}